// round 16
// baseline (speedup 1.0000x reference)
#include <cuda_runtime.h>
#include <cuda_bf16.h>
#include <math.h>
#include <stdint.h>

#define NEGF -1e32f
typedef __nv_bfloat16 bf16;

// ---------------- scratch (static device globals; no allocation) ----------------
__device__ float g_v[4 * 16 * 1024 * 64];     // v proj fp32 [b*h, s, dk]
__device__ float g_x[4096 * 1024];            // pre-LN

#define NBIG (4096 * 1024)
#define NW   (1024 * 1024)
#define NP   (4L * 16 * 1024 * 1024)
__device__ bf16 g_aqh[NBIG], g_aql[NBIG];     // split(query)
__device__ bf16 g_akh[NBIG], g_akl[NBIG];     // split(key)
__device__ bf16 g_avh[NBIG], g_avl[NBIG];     // split(values)
__device__ bf16 g_wqh[NW],  g_wql[NW];        // split(Wq^T)  [n][k]
__device__ bf16 g_wvh[NW],  g_wvl[NW];
__device__ bf16 g_woh[NW],  g_wol[NW];
__device__ bf16 g_qh[NBIG], g_ql[NBIG];       // split q proj [b*h,s,dk]
__device__ bf16 g_kh[NBIG], g_kl[NBIG];
__device__ bf16 g_vth[NBIG], g_vtl[NBIG];     // split V^T per head [b*h,dk,s]
__device__ bf16 g_ch[NBIG], g_cl[NBIG];       // split concat [b*s,d]
__device__ bf16 g_ph[NP],  g_pl[NP];          // split final P (zero-init; only causal
                                              // quads are ever written -> rest stays 0)

__device__ __forceinline__ uint32_t pack2(bf16 a, bf16 b)
{
    __nv_bfloat162 t; t.x = a; t.y = b;
    return *reinterpret_cast<uint32_t*>(&t);
}
__device__ __forceinline__ void split1(float v, bf16& h, bf16& l)
{
    h = __float2bfloat16(v);
    l = __float2bfloat16(v - __bfloat162float(h));
}
__device__ __forceinline__ uint32_t cvta_smem(const void* p)
{
    uint32_t a;
    asm("{ .reg .u64 t; cvta.to.shared.u64 t, %1; cvt.u32.u64 %0, t; }"
        : "=r"(a) : "l"(p));
    return a;
}
__device__ __forceinline__ void cp16(uint32_t dst, const void* src)
{
    asm volatile("cp.async.cg.shared.global [%0], [%1], 16;\n"
                 :: "r"(dst), "l"(src));
}
__device__ __forceinline__ void cp_commit()
{
    asm volatile("cp.async.commit_group;\n" ::: "memory");
}
template <int N>
__device__ __forceinline__ void cp_wait()
{
    asm volatile("cp.async.wait_group %0;\n" :: "n"(N) : "memory");
}
__device__ __forceinline__ void ldsm4(uint32_t* r, uint32_t addr)
{
    asm volatile("ldmatrix.sync.aligned.m8n8.x4.shared.b16 {%0,%1,%2,%3}, [%4];"
                 : "=r"(r[0]), "=r"(r[1]), "=r"(r[2]), "=r"(r[3]) : "r"(addr));
}

// ===========================================================================
// fused elementwise split of the 3 inputs: blockIdx.y selects tensor
// ===========================================================================
__global__ void __launch_bounds__(256)
split3_k(const float* __restrict__ x0, const float* __restrict__ x1,
         const float* __restrict__ x2,
         bf16* __restrict__ h0, bf16* __restrict__ l0,
         bf16* __restrict__ h1, bf16* __restrict__ l1,
         bf16* __restrict__ h2, bf16* __restrict__ l2)
{
    const int sel = blockIdx.y;
    const float* x = sel == 0 ? x0 : (sel == 1 ? x1 : x2);
    bf16* hi = sel == 0 ? h0 : (sel == 1 ? h1 : h2);
    bf16* lo = sel == 0 ? l0 : (sel == 1 ? l1 : l2);
    int i = blockIdx.x * 256 + threadIdx.x;
    float4 v = reinterpret_cast<const float4*>(x)[i];
    bf16 h[4], l[4];
    float f[4] = {v.x, v.y, v.z, v.w};
#pragma unroll
    for (int j = 0; j < 4; j++) split1(f[j], h[j], l[j]);
    reinterpret_cast<uint2*>(hi)[i] = *reinterpret_cast<uint2*>(h);
    reinterpret_cast<uint2*>(lo)[i] = *reinterpret_cast<uint2*>(l);
}

// ===========================================================================
// fused transpose + split of the 3 weights: W[k][n] -> Wt_hi/lo[n][k]
// blockIdx.z selects {Wq, Wv, Wo}
// ===========================================================================
__global__ void __launch_bounds__(256)
tsplit3_k(const float* __restrict__ W0, const float* __restrict__ W1,
          const float* __restrict__ W2)
{
    __shared__ float t[32][33];
    const int sel = blockIdx.z;
    const float* W = sel == 0 ? W0 : (sel == 1 ? W1 : W2);
    bf16* th = sel == 0 ? g_wqh : (sel == 1 ? g_wvh : g_woh);
    bf16* tl = sel == 0 ? g_wql : (sel == 1 ? g_wvl : g_wol);
    const int n0 = blockIdx.x * 32, k0 = blockIdx.y * 32;
    const int tx = threadIdx.x & 31, ty = threadIdx.x >> 5;   // 32 x 8
    for (int i = ty; i < 32; i += 8)
        t[i][tx] = W[(size_t)(k0 + i) * 1024 + n0 + tx];
    __syncthreads();
    for (int i = ty; i < 32; i += 8) {
        bf16 h, l; split1(t[tx][i], h, l);
        size_t o = (size_t)(n0 + i) * 1024 + k0 + tx;
        th[o] = h; tl[o] = l;
    }
}

// ===========================================================================
// per-head transpose + split of V: [b*h, s, 64] fp32 -> [b*h, 64, s] bf16 hi/lo
// ===========================================================================
__global__ void __launch_bounds__(256)
vtsplit_k(const float* __restrict__ v, bf16* __restrict__ th, bf16* __restrict__ tl)
{
    __shared__ float t[32][33];
    const int dd0 = blockIdx.x * 32, s0 = blockIdx.y * 32, bh = blockIdx.z;
    const int tx = threadIdx.x, ty = threadIdx.y;   // 32 x 8
    for (int i = ty; i < 32; i += 8)
        t[i][tx] = v[((size_t)bh * 1024 + s0 + i) * 64 + dd0 + tx];  // t[s][dd]
    __syncthreads();
    for (int i = ty; i < 32; i += 8) {
        bf16 h, l; split1(t[tx][i], h, l);              // V[s0+tx][dd0+i]
        size_t o = ((size_t)bh * 64 + dd0 + i) * 1024 + s0 + tx;
        th[o] = h; tl[o] = l;
    }
}

// ===========================================================================
// bf16x3 mma.sync GEMM, cp.async 2-stage pipeline, BK=32, term-reordered MMAs,
// ldmatrix.x4 loads, __launch_bounds__(256,2) -> 128 regs, 2 CTAs/SM.
// SINGLE sync per chunk: wait -> sync -> prefetch(c+1) -> compute(c).
// (Safe: prefetch(c+1) overwrites the stage consumed at c-1, which the sync
//  protects; load(c+1) still overlaps compute(c). At 2 CTAs/SM the residual
//  wait stall is covered by the co-resident CTA.)
// MODE 5: FUSED q/k/v projections (bz selects); MODE 1: QK^T; MODE 2: PV;
// MODE 3: Wo.
// ===========================================================================
__device__ __forceinline__ void mma16816(float* c, const uint32_t* a, const uint32_t* b)
{
    asm volatile(
        "mma.sync.aligned.m16n8k16.row.col.f32.bf16.bf16.f32 "
        "{%0,%1,%2,%3}, {%4,%5,%6,%7}, {%8,%9}, {%0,%1,%2,%3};\n"
        : "+f"(c[0]), "+f"(c[1]), "+f"(c[2]), "+f"(c[3])
        : "r"(a[0]), "r"(a[1]), "r"(a[2]), "r"(a[3]), "r"(b[0]), "r"(b[1]));
}

template <int MODE, int BN, int WM, int WN>
__global__ void __launch_bounds__(256, 2)
bmma2_k(const bf16* __restrict__ Ah_, const bf16* __restrict__ Al_,
        const bf16* __restrict__ Bh_, const bf16* __restrict__ Bl_,
        float* __restrict__ Cg, bf16* __restrict__ Oh, bf16* __restrict__ Ol,
        const float* __restrict__ bias, const float* __restrict__ resid,
        int K, int lda, int ldb, long sA, long sB, long sC)
{
    constexpr int BM = 128, LDS = 40;
    constexpr int WTM = BM / WM, WTN = BN / WN;
    constexpr int TI = WTM / 16, UI = WTN / 8;
    constexpr int A_ELE = BM * LDS;             // bf16 elems per A array
    constexpr int B_ELE = BN * LDS;
    constexpr int STAGE = 2 * A_ELE + 2 * B_ELE;  // bf16 elems per stage

    extern __shared__ bf16 smem[];              // 2 stages

    const int bx = blockIdx.x, by = blockIdx.y, bz = blockIdx.z;
    if (MODE == 1) { if (bx > by) return; }

    const bf16 *pAh, *pAl, *pBh, *pBl;
    if (MODE == 5) {
        if (bz == 0)      { pAh = g_aqh; pAl = g_aql; pBh = g_wqh; pBl = g_wql; }
        else if (bz == 1) { pAh = g_akh; pAl = g_akl; pBh = g_wqh; pBl = g_wql; }
        else              { pAh = g_avh; pAl = g_avl; pBh = g_wvh; pBl = g_wvl; }
    } else {
        pAh = Ah_ + (size_t)bz * sA;
        pAl = Al_ + (size_t)bz * sA;
        pBh = Bh_ + (size_t)bz * sB;
        pBl = Bl_ + (size_t)bz * sB;
    }

    const int m0 = by * BM, n0 = bx * BN;
    const int tid = threadIdx.x;
    const int warp = tid >> 5, lane = tid & 31;
    const int wm = warp / WN, wn = warp % WN;
    const int arow = tid >> 2;                  // 0..63
    const int acol = (tid & 3) * 8;             // 8-bf16 chunk

    const uint32_t smem_u = cvta_smem(smem);

    float acc[TI][UI][4];
#pragma unroll
    for (int t = 0; t < TI; t++)
#pragma unroll
        for (int u = 0; u < UI; u++)
#pragma unroll
            for (int r = 0; r < 4; r++) acc[t][u][r] = 0.f;

    const int kend = (MODE == 2) ? min(K, m0 + BM) : K;
    const int nch = kend >> 5;

    auto prefetch = [&](int c, int st) {
        const int k0 = c << 5;
        const uint32_t base = smem_u + (uint32_t)st * STAGE * 2;
#pragma unroll
        for (int it = 0; it < 2; it++) {
            int r = it * 64 + arow;
            uint32_t so = (uint32_t)(r * LDS + acol) * 2;
            size_t go = (size_t)(m0 + r) * lda + k0 + acol;
            cp16(base + so, pAh + go);
            cp16(base + A_ELE * 2 + so, pAl + go);
        }
#pragma unroll
        for (int it = 0; it < BN / 64; it++) {
            int r = it * 64 + arow;
            uint32_t so = (uint32_t)(r * LDS + acol) * 2;
            size_t go = (size_t)(n0 + r) * ldb + k0 + acol;
            cp16(base + 2 * A_ELE * 2 + so, pBh + go);
            cp16(base + (2 * A_ELE + B_ELE) * 2 + so, pBl + go);
        }
        cp_commit();
    };

    // ldmatrix lane geometry (constant per thread)
    const int a_row_f = lane & 15;              // row within 16-row fragment
    const int a_col_f = (lane >> 4) * 8;        // col half (0 / 8)
    const int b_row_f = (lane & 7) + ((lane >> 4) & 1) * 8;  // row within 16
    const int b_col_f = ((lane >> 3) & 1) * 8;  // col half (0 / 8)

    auto compute = [&](int st) {
        const uint32_t sbase  = smem_u + (uint32_t)st * STAGE * 2;
        const uint32_t aoff_h = sbase;
        const uint32_t aoff_l = sbase + A_ELE * 2;
        const uint32_t boff_h = sbase + 2 * A_ELE * 2;
        const uint32_t boff_l = sbase + (2 * A_ELE + B_ELE) * 2;
#pragma unroll
        for (int ks = 0; ks < 2; ks++) {
            const int c = ks * 16;
            uint32_t ah[TI][4], al[TI][4], bh[UI][2], bl[UI][2];
#pragma unroll
            for (int t = 0; t < TI; t++) {
                int r = wm * WTM + t * 16 + a_row_f;
                uint32_t off = (uint32_t)(r * LDS + c + a_col_f) * 2;
                ldsm4(ah[t], aoff_h + off);
                ldsm4(al[t], aoff_l + off);
            }
#pragma unroll
            for (int up = 0; up < UI / 2; up++) {
                int n = wn * WTN + up * 16 + b_row_f;
                uint32_t off = (uint32_t)(n * LDS + c + b_col_f) * 2;
                ldsm4(&bh[up * 2][0], boff_h + off);
                ldsm4(&bl[up * 2][0], boff_l + off);
            }
            // term-reordered: accumulator reuse spaced TI*UI mmas apart
#pragma unroll
            for (int t = 0; t < TI; t++)
#pragma unroll
                for (int u = 0; u < UI; u++) mma16816(acc[t][u], ah[t], bh[u]);
#pragma unroll
            for (int t = 0; t < TI; t++)
#pragma unroll
                for (int u = 0; u < UI; u++) mma16816(acc[t][u], al[t], bh[u]);
#pragma unroll
            for (int t = 0; t < TI; t++)
#pragma unroll
                for (int u = 0; u < UI; u++) mma16816(acc[t][u], ah[t], bl[u]);
        }
    };

    // single-sync pipeline: wait(c) -> barrier -> prefetch(c+1) -> compute(c)
    prefetch(0, 0);
    for (int c = 0; c < nch; c++) {
        cp_wait<0>();
        __syncthreads();
        if (c + 1 < nch) prefetch(c + 1, (c + 1) & 1);
        compute(c & 1);
    }

    // ---- epilogue (pairs; n even) ----
#pragma unroll
    for (int t = 0; t < TI; t++) {
#pragma unroll
        for (int u = 0; u < UI; u++) {
            int m = m0 + wm * WTM + t * 16 + (lane >> 2);
            int n = n0 + wn * WTN + u * 8 + (lane & 3) * 2;
#pragma unroll
            for (int half = 0; half < 2; half++) {
                int mm = m + half * 8;
                float v0 = acc[t][u][half * 2 + 0];
                float v1 = acc[t][u][half * 2 + 1];
                if (MODE == 5) {
                    int b = mm >> 10, s = mm & 1023;
                    int h = n >> 6, dd = n & 63;
                    size_t o = ((size_t)((b * 16 + h) * 1024 + s)) * 64 + dd;
                    if (bz < 2) {                    // q/k: split bf16 store
                        bf16* OH = bz == 0 ? g_qh : g_kh;
                        bf16* OL = bz == 0 ? g_ql : g_kl;
                        bf16 h0, l0, h1, l1;
                        split1(v0 + bias[n], h0, l0);
                        split1(v1 + bias[n + 1], h1, l1);
                        *reinterpret_cast<uint32_t*>(&OH[o]) = pack2(h0, h1);
                        *reinterpret_cast<uint32_t*>(&OL[o]) = pack2(l0, l1);
                    } else {                         // v: fp32 store (bias in resid)
                        float2 o2 = make_float2(v0 + resid[n], v1 + resid[n + 1]);
                        *reinterpret_cast<float2*>(&g_v[o]) = o2;
                    }
                } else if (MODE == 1) {              // scores
                    float* C = Cg + (size_t)bz * sC;
                    float2 o2 = make_float2(v0 * 0.125f, v1 * 0.125f);
                    *reinterpret_cast<float2*>(&C[(size_t)mm * 1024 + n]) = o2;
                } else if (MODE == 2) {              // split concat (PV)
                    int b = bz >> 4, hh = bz & 15;
                    size_t o = ((size_t)(b * 1024 + mm)) * 1024 + hh * 64 + n;
                    bf16 h0, l0, h1, l1;
                    split1(v0, h0, l0);
                    split1(v1, h1, l1);
                    *reinterpret_cast<uint32_t*>(&Oh[o]) = pack2(h0, h1);
                    *reinterpret_cast<uint32_t*>(&Ol[o]) = pack2(l0, l1);
                } else {                             // MODE 3: Wo
                    float2 rr = *reinterpret_cast<const float2*>(
                        &resid[(size_t)mm * 1024 + n]);
                    float2 o2 = make_float2(v0 + bias[n] + rr.x,
                                            v1 + bias[n + 1] + rr.y);
                    *reinterpret_cast<float2*>(&Cg[(size_t)mm * 1024 + n]) = o2;
                }
            }
        }
    }
}

// ---------------------------------------------------------------------------
// Row pass, TWO ROWS PER BLOCK (128 threads/row), one sync per reduction.
// Rows paired (i, 1023-i) for load balance. (Proven Round-13 shape.)
// ---------------------------------------------------------------------------
__global__ void __launch_bounds__(256)
rowpass2_k(float* __restrict__ S, const float* __restrict__ gammas,
           bf16* __restrict__ Ph, bf16* __restrict__ Pl)
{
    __shared__ float sm_m1[8], sm_s1[8], sm_t[16], sm_m2[8], sm_s2[8], sm_mx[8];

    const int tid  = threadIdx.x;
    const int g    = tid >> 7;                 // row group 0/1
    const int lt   = tid & 127;                // thread within group
    const int w    = lt >> 5;                  // warp within group 0..3
    const int lane = tid & 31;
    const int bx = blockIdx.x, bh = blockIdx.y;
    const int i = g ? (1023 - bx) : bx;
    const float gamma = -fabsf(gammas[bh & 15]);
    const size_t ro = ((size_t)bh << 20) + ((size_t)i << 10);
    float4* rowv = reinterpret_cast<float4*>(S + ro);

    const int ca = 4 * lt;                     // quad A cols [ca, ca+3]
    const int cb = 512 + 4 * lt;               // quad B cols
    const bool liveA = ca < i, liveB = cb < i;

    float sA[4] = {0.f, 0.f, 0.f, 0.f}, sB[4] = {0.f, 0.f, 0.f, 0.f};
    if (liveA) { float4 v = rowv[lt];       sA[0]=v.x; sA[1]=v.y; sA[2]=v.z; sA[3]=v.w; }
    if (liveB) { float4 v = rowv[128 + lt]; sB[0]=v.x; sB[1]=v.y; sB[2]=v.z; sB[3]=v.w; }

    float lgA[4], lgB[4];
#pragma unroll
    for (int l = 0; l < 4; l++) {
        lgA[l] = (ca + l < i) ? sA[l] : NEGF;
        lgB[l] = (cb + l < i) ? sB[l] : NEGF;
    }

    // ---- softmax-1 max (1 sync) ----
    float m = NEGF;
#pragma unroll
    for (int l = 0; l < 4; l++) m = fmaxf(m, fmaxf(lgA[l], lgB[l]));
#pragma unroll
    for (int o = 16; o; o >>= 1) m = fmaxf(m, __shfl_xor_sync(0xffffffffu, m, o));
    if (lane == 0) sm_m1[g * 4 + w] = m;
    __syncthreads();
    const float m1 = fmaxf(fmaxf(sm_m1[g*4+0], sm_m1[g*4+1]),
                           fmaxf(sm_m1[g*4+2], sm_m1[g*4+3]));

    // ---- exp + sum-1 (1 sync) ----
    float pA[4], pB[4];
    float s = 0.f;
#pragma unroll
    for (int l = 0; l < 4; l++) {
        pA[l] = __expf(lgA[l] - m1); s += pA[l];
        pB[l] = __expf(lgB[l] - m1); s += pB[l];
    }
#pragma unroll
    for (int o = 16; o; o >>= 1) s += __shfl_xor_sync(0xffffffffu, s, o);
    if (lane == 0) sm_s1[g * 4 + w] = s;
    __syncthreads();
    const float inv1 = 1.0f / (sm_s1[g*4+0] + sm_s1[g*4+1] + sm_s1[g*4+2] + sm_s1[g*4+3]);
#pragma unroll
    for (int l = 0; l < 4; l++) { pA[l] *= inv1; pB[l] *= inv1; }

    // ---- cumsum: warp scans + cross-warp prefix table (1 sync) ----
    const float localA = pA[0] + pA[1] + pA[2] + pA[3];
    const float localB = pB[0] + pB[1] + pB[2] + pB[3];
    float incA = localA, incB = localB;
#pragma unroll
    for (int o = 1; o < 32; o <<= 1) {
        float na = __shfl_up_sync(0xffffffffu, incA, o);
        float nb = __shfl_up_sync(0xffffffffu, incB, o);
        if (lane >= o) { incA += na; incB += nb; }
    }
    if (lane == 31) { sm_t[g * 8 + w] = incA; sm_t[g * 8 + 4 + w] = incB; }
    __syncthreads();
    float prevA = 0.f, prevB = 0.f;
    for (int w2 = 0; w2 < 4; w2++) {
        if (w2 < w) { prevA += sm_t[g * 8 + w2]; prevB += sm_t[g * 8 + 4 + w2]; }
    }
    const float totA = sm_t[g*8+0] + sm_t[g*8+1] + sm_t[g*8+2] + sm_t[g*8+3];
    const float totB = sm_t[g*8+4] + sm_t[g*8+5] + sm_t[g*8+6] + sm_t[g*8+7];
    const float preA = prevA + (incA - localA);
    const float preB = totA + prevB + (incB - localB);
    const float T = totA + totB;

    // ---- distance decay -> rescored logits ----
    float run = preA;
#pragma unroll
    for (int l = 0; l < 4; l++) {
        run += pA[l];
        float pe  = fabsf((float)(i - (ca + l)));
        float ds  = sqrtf(fmaxf(0.f, (T - run) * pe));
        float eff = fminf(fmaxf(__expf(ds * gamma), 1e-5f), 1e5f);
        lgA[l] = (ca + l < i) ? sA[l] * eff : NEGF;
    }
    run = preB;
#pragma unroll
    for (int l = 0; l < 4; l++) {
        run += pB[l];
        float pe  = fabsf((float)(i - (cb + l)));
        float ds  = sqrtf(fmaxf(0.f, (T - run) * pe));
        float eff = fminf(fmaxf(__expf(ds * gamma), 1e-5f), 1e5f);
        lgB[l] = (cb + l < i) ? sB[l] * eff : NEGF;
    }

    // ---- softmax-2 max (1 sync) ----
    m = NEGF;
#pragma unroll
    for (int l = 0; l < 4; l++) m = fmaxf(m, fmaxf(lgA[l], lgB[l]));
#pragma unroll
    for (int o = 16; o; o >>= 1) m = fmaxf(m, __shfl_xor_sync(0xffffffffu, m, o));
    if (lane == 0) sm_m2[g * 4 + w] = m;
    __syncthreads();
    const float m2 = fmaxf(fmaxf(sm_m2[g*4+0], sm_m2[g*4+1]),
                           fmaxf(sm_m2[g*4+2], sm_m2[g*4+3]));

    // ---- exp + sum-2 (1 sync) ----
    s = 0.f;
#pragma unroll
    for (int l = 0; l < 4; l++) {
        pA[l] = __expf(lgA[l] - m2); s += pA[l];
        pB[l] = __expf(lgB[l] - m2); s += pB[l];
    }
#pragma unroll
    for (int o = 16; o; o >>= 1) s += __shfl_xor_sync(0xffffffffu, s, o);
    if (lane == 0) sm_s2[g * 4 + w] = s;
    __syncthreads();
    const float inv2 = 1.0f / (sm_s2[g*4+0] + sm_s2[g*4+1] + sm_s2[g*4+2] + sm_s2[g*4+3]);

    // ---- zero-mask + row max (1 sync) ----
    float mx = 0.f;
#pragma unroll
    for (int l = 0; l < 4; l++) {
        pA[l] = (ca + l < i) ? pA[l] * inv2 : 0.f;
        pB[l] = (cb + l < i) ? pB[l] * inv2 : 0.f;
        mx = fmaxf(mx, fmaxf(pA[l], pB[l]));
    }
#pragma unroll
    for (int o = 16; o; o >>= 1) mx = fmaxf(mx, __shfl_xor_sync(0xffffffffu, mx, o));
    if (lane == 0) sm_mx[g * 4 + w] = mx;
    __syncthreads();
    const float mxr = fmaxf(fmaxf(sm_mx[g*4+0], sm_mx[g*4+1]),
                            fmaxf(sm_mx[g*4+2], sm_mx[g*4+3]));
    const float scale = fminf(1.0f / mxr, 5.0f);

    // ---- writes: full fp32 row (masked entries are exact 0); causal bf16 ----
    float4 ovA = make_float4(pA[0]*scale, pA[1]*scale, pA[2]*scale, pA[3]*scale);
    float4 ovB = make_float4(pB[0]*scale, pB[1]*scale, pB[2]*scale, pB[3]*scale);
    rowv[lt] = ovA;
    rowv[128 + lt] = ovB;
    if (liveA) {
        bf16 hh[4], ll[4];
#pragma unroll
        for (int l = 0; l < 4; l++) split1((&ovA.x)[l], hh[l], ll[l]);
        reinterpret_cast<uint2*>(Ph + ro)[lt] = *reinterpret_cast<uint2*>(hh);
        reinterpret_cast<uint2*>(Pl + ro)[lt] = *reinterpret_cast<uint2*>(ll);
    }
    if (liveB) {
        bf16 hh[4], ll[4];
#pragma unroll
        for (int l = 0; l < 4; l++) split1((&ovB.x)[l], hh[l], ll[l]);
        reinterpret_cast<uint2*>(Ph + ro)[128 + lt] = *reinterpret_cast<uint2*>(hh);
        reinterpret_cast<uint2*>(Pl + ro)[128 + lt] = *reinterpret_cast<uint2*>(ll);
    }
}

// ---------------------------------------------------------------------------
// block reduction helper (LN only)
// ---------------------------------------------------------------------------
template <bool IS_MAX>
__device__ __forceinline__ float blk_reduce(float v, float* red, int tid)
{
    const int lane = tid & 31, wid = tid >> 5;
#pragma unroll
    for (int o = 16; o; o >>= 1) {
        float t = __shfl_xor_sync(0xffffffffu, v, o);
        v = IS_MAX ? fmaxf(v, t) : (v + t);
    }
    __syncthreads();
    if (lane == 0) red[wid] = v;
    __syncthreads();
    if (tid == 0) {
        float r = red[0];
        for (int w = 1; w < 8; w++) r = IS_MAX ? fmaxf(r, red[w]) : (r + red[w]);
        red[8] = r;
    }
    __syncthreads();
    return red[8];
}

// ---------------------------------------------------------------------------
// LayerNorm over last dim (1024), one block per row.
// ---------------------------------------------------------------------------
__global__ void __launch_bounds__(256)
ln_k(const float* __restrict__ X, const float* __restrict__ w,
     const float* __restrict__ b, float* __restrict__ out)
{
    __shared__ float red[9];
    const int m = blockIdx.x, tid = threadIdx.x;
    const float* xr = X + (size_t)m * 1024u;

    float4 xv = reinterpret_cast<const float4*>(xr)[tid];
    float sx = xv.x + xv.y + xv.z + xv.w;
    float sq = xv.x * xv.x + xv.y * xv.y + xv.z * xv.z + xv.w * xv.w;

    float sum   = blk_reduce<false>(sx, red, tid);
    float sumsq = blk_reduce<false>(sq, red, tid);
    float mu   = sum * (1.0f / 1024.0f);
    float var  = sumsq * (1.0f / 1024.0f) - mu * mu;
    float rstd = rsqrtf(var + 1e-5f);

    float4 wv = reinterpret_cast<const float4*>(w)[tid];
    float4 bv = reinterpret_cast<const float4*>(b)[tid];
    float4 ov;
    ov.x = (xv.x - mu) * rstd * wv.x + bv.x;
    ov.y = (xv.y - mu) * rstd * wv.y + bv.y;
    ov.z = (xv.z - mu) * rstd * wv.z + bv.z;
    ov.w = (xv.w - mu) * rstd * wv.w + bv.w;
    reinterpret_cast<float4*>(out + (size_t)m * 1024u)[tid] = ov;
}

// ---------------------------------------------------------------------------
extern "C" void kernel_launch(void* const* d_in, const int* in_sizes, int n_in,
                              void* d_out, int out_size)
{
    const float* query  = (const float*)d_in[0];
    const float* key    = (const float*)d_in[1];
    const float* values = (const float*)d_in[2];
    const float* Wq     = (const float*)d_in[3];
    const float* bq     = (const float*)d_in[4];
    const float* Wv     = (const float*)d_in[5];
    const float* bv     = (const float*)d_in[6];
    const float* Wo     = (const float*)d_in[7];
    const float* bo     = (const float*)d_in[8];
    const float* gammas = (const float*)d_in[9];
    const float* ln_w   = (const float*)d_in[10];
    const float* ln_b   = (const float*)d_in[11];

    float* out    = (float*)d_out;                       // [4,1024,1024]
    float* scores = out + (size_t)4 * 1024 * 1024;       // [4,16,1024,1024]

    float *vp, *xp;
    cudaGetSymbolAddress((void**)&vp, g_v);
    cudaGetSymbolAddress((void**)&xp, g_x);

    bf16 *aqh,*aql,*akh,*akl,*avh,*avl;
    bf16 *qh,*ql,*kh,*kl,*vth,*vtl,*ch,*cl,*ph,*pl,*woh,*wol;
    cudaGetSymbolAddress((void**)&aqh, g_aqh); cudaGetSymbolAddress((void**)&aql, g_aql);
    cudaGetSymbolAddress((void**)&akh, g_akh); cudaGetSymbolAddress((void**)&akl, g_akl);
    cudaGetSymbolAddress((void**)&avh, g_avh); cudaGetSymbolAddress((void**)&avl, g_avl);
    cudaGetSymbolAddress((void**)&woh, g_woh); cudaGetSymbolAddress((void**)&wol, g_wol);
    cudaGetSymbolAddress((void**)&qh,  g_qh);  cudaGetSymbolAddress((void**)&ql,  g_ql);
    cudaGetSymbolAddress((void**)&kh,  g_kh);  cudaGetSymbolAddress((void**)&kl,  g_kl);
    cudaGetSymbolAddress((void**)&vth, g_vth); cudaGetSymbolAddress((void**)&vtl, g_vtl);
    cudaGetSymbolAddress((void**)&ch,  g_ch);  cudaGetSymbolAddress((void**)&cl,  g_cl);
    cudaGetSymbolAddress((void**)&ph,  g_ph);  cudaGetSymbolAddress((void**)&pl,  g_pl);

    const int NB4 = NBIG / 4 / 256;

    // dynamic smem sizes: 2 stages * (2*A + 2*B) * 40 * 2 bytes
    const int SM128 = 2 * (2 * 128 * 40 + 2 * 128 * 40) * 2;   // 81920
    const int SM64  = 2 * (2 * 128 * 40 + 2 * 64 * 40) * 2;    // 61440

    cudaFuncSetAttribute((const void*)bmma2_k<5, 128, 2, 4>,
        cudaFuncAttributeMaxDynamicSharedMemorySize, SM128);
    cudaFuncSetAttribute((const void*)bmma2_k<1, 128, 2, 4>,
        cudaFuncAttributeMaxDynamicSharedMemorySize, SM128);
    cudaFuncSetAttribute((const void*)bmma2_k<3, 128, 2, 4>,
        cudaFuncAttributeMaxDynamicSharedMemorySize, SM128);
    cudaFuncSetAttribute((const void*)bmma2_k<2, 64, 4, 2>,
        cudaFuncAttributeMaxDynamicSharedMemorySize, SM64);

    // 0) fused input split + fused weight transpose-splits (launches 1-2)
    split3_k<<<dim3(NB4, 3), 256>>>(query, key, values,
                                    aqh, aql, akh, akl, avh, avl);
    tsplit3_k<<<dim3(32, 32, 3), 256>>>(Wq, Wv, Wo);

    // 1) FUSED q/k/v projections (launch 3)
    bmma2_k<5, 128, 2, 4><<<dim3(8, 32, 3), 256, SM128>>>(
        nullptr, nullptr, nullptr, nullptr, nullptr, nullptr, nullptr,
        bq, bv, 1024, 1024, 1024, 0, 0, 0);
    vtsplit_k<<<dim3(2, 32, 64), dim3(32, 8)>>>(vp, vth, vtl);   // launch 4

    // 2) scores = Q K^T / 8 per head (launch 5)
    bmma2_k<1, 128, 2, 4><<<dim3(8, 8, 64), 256, SM128>>>(
        qh, ql, kh, kl, scores, nullptr, nullptr, nullptr, nullptr,
        64, 64, 64, 1024L * 64, 1024L * 64, 1024L * 1024);

    // 3) row pass (launch 6 = ncu capture target)
    rowpass2_k<<<dim3(512, 64), 256>>>(scores, gammas, ph, pl);

    // 4) concat = P @ V (causal K truncation, split output)
    bmma2_k<2, 64, 4, 2><<<dim3(1, 8, 64), 256, SM64>>>(
        ph, pl, vth, vtl, nullptr, ch, cl, nullptr, nullptr,
        1024, 1024, 1024, 1024L * 1024, 64L * 1024, 0);

    // 5) x = query + concat @ Wo + bo
    bmma2_k<3, 128, 2, 4><<<dim3(8, 32), 256, SM128>>>(
        ch, cl, woh, wol, xp, nullptr, nullptr,
        bo, query, 1024, 1024, 1024, 0, 0, 0);

    // 6) out = LayerNorm(x)
    ln_k<<<4096, 256>>>(xp, ln_w, ln_b, out);
}

// round 17
// speedup vs baseline: 1.0197x; 1.0197x over previous
#include <cuda_runtime.h>
#include <cuda_bf16.h>
#include <math.h>
#include <stdint.h>

#define NEGF -1e32f
typedef __nv_bfloat16 bf16;

// ---------------- scratch (static device globals; no allocation) ----------------
__device__ float g_x[4096 * 1024];            // pre-LN

#define NBIG (4096 * 1024)
#define NW   (1024 * 1024)
#define NP   (4L * 16 * 1024 * 1024)
__device__ bf16 g_aqh[NBIG], g_aql[NBIG];     // split(query)
__device__ bf16 g_akh[NBIG], g_akl[NBIG];     // split(key)
__device__ bf16 g_avh[NBIG], g_avl[NBIG];     // split(values)
__device__ bf16 g_wqh[NW],  g_wql[NW];        // split(Wq^T)  [n][k]
__device__ bf16 g_wvh[NW],  g_wvl[NW];
__device__ bf16 g_woh[NW],  g_wol[NW];
__device__ bf16 g_qh[NBIG], g_ql[NBIG];       // split q proj [b*h,s,dk]
__device__ bf16 g_kh[NBIG], g_kl[NBIG];
__device__ bf16 g_vth[NBIG], g_vtl[NBIG];     // split V^T per head [b*h,dk,s]
__device__ bf16 g_ch[NBIG], g_cl[NBIG];       // split concat [b*s,d]
__device__ bf16 g_ph[NP],  g_pl[NP];          // split final P (zero-init; only causal
                                              // quads are ever written -> rest stays 0)

__device__ __forceinline__ uint32_t pack2(bf16 a, bf16 b)
{
    __nv_bfloat162 t; t.x = a; t.y = b;
    return *reinterpret_cast<uint32_t*>(&t);
}
__device__ __forceinline__ void split1(float v, bf16& h, bf16& l)
{
    h = __float2bfloat16(v);
    l = __float2bfloat16(v - __bfloat162float(h));
}
__device__ __forceinline__ uint32_t cvta_smem(const void* p)
{
    uint32_t a;
    asm("{ .reg .u64 t; cvta.to.shared.u64 t, %1; cvt.u32.u64 %0, t; }"
        : "=r"(a) : "l"(p));
    return a;
}
__device__ __forceinline__ void cp16(uint32_t dst, const void* src)
{
    asm volatile("cp.async.cg.shared.global [%0], [%1], 16;\n"
                 :: "r"(dst), "l"(src));
}
__device__ __forceinline__ void cp_commit()
{
    asm volatile("cp.async.commit_group;\n" ::: "memory");
}
template <int N>
__device__ __forceinline__ void cp_wait()
{
    asm volatile("cp.async.wait_group %0;\n" :: "n"(N) : "memory");
}
__device__ __forceinline__ void ldsm4(uint32_t* r, uint32_t addr)
{
    asm volatile("ldmatrix.sync.aligned.m8n8.x4.shared.b16 {%0,%1,%2,%3}, [%4];"
                 : "=r"(r[0]), "=r"(r[1]), "=r"(r[2]), "=r"(r[3]) : "r"(addr));
}

// ===========================================================================
// fused elementwise split of the 3 inputs: blockIdx.y selects tensor
// ===========================================================================
__global__ void __launch_bounds__(256)
split3_k(const float* __restrict__ x0, const float* __restrict__ x1,
         const float* __restrict__ x2,
         bf16* __restrict__ h0, bf16* __restrict__ l0,
         bf16* __restrict__ h1, bf16* __restrict__ l1,
         bf16* __restrict__ h2, bf16* __restrict__ l2)
{
    const int sel = blockIdx.y;
    const float* x = sel == 0 ? x0 : (sel == 1 ? x1 : x2);
    bf16* hi = sel == 0 ? h0 : (sel == 1 ? h1 : h2);
    bf16* lo = sel == 0 ? l0 : (sel == 1 ? l1 : l2);
    int i = blockIdx.x * 256 + threadIdx.x;
    float4 v = reinterpret_cast<const float4*>(x)[i];
    bf16 h[4], l[4];
    float f[4] = {v.x, v.y, v.z, v.w};
#pragma unroll
    for (int j = 0; j < 4; j++) split1(f[j], h[j], l[j]);
    reinterpret_cast<uint2*>(hi)[i] = *reinterpret_cast<uint2*>(h);
    reinterpret_cast<uint2*>(lo)[i] = *reinterpret_cast<uint2*>(l);
}

// ===========================================================================
// fused transpose + split of the 3 weights: W[k][n] -> Wt_hi/lo[n][k]
// blockIdx.z selects {Wq, Wv, Wo}
// ===========================================================================
__global__ void __launch_bounds__(256)
tsplit3_k(const float* __restrict__ W0, const float* __restrict__ W1,
          const float* __restrict__ W2)
{
    __shared__ float t[32][33];
    const int sel = blockIdx.z;
    const float* W = sel == 0 ? W0 : (sel == 1 ? W1 : W2);
    bf16* th = sel == 0 ? g_wqh : (sel == 1 ? g_wvh : g_woh);
    bf16* tl = sel == 0 ? g_wql : (sel == 1 ? g_wvl : g_wol);
    const int n0 = blockIdx.x * 32, k0 = blockIdx.y * 32;
    const int tx = threadIdx.x & 31, ty = threadIdx.x >> 5;   // 32 x 8
    for (int i = ty; i < 32; i += 8)
        t[i][tx] = W[(size_t)(k0 + i) * 1024 + n0 + tx];
    __syncthreads();
    for (int i = ty; i < 32; i += 8) {
        bf16 h, l; split1(t[tx][i], h, l);
        size_t o = (size_t)(n0 + i) * 1024 + k0 + tx;
        th[o] = h; tl[o] = l;
    }
}

// ===========================================================================
// bf16x3 mma.sync GEMM, cp.async 2-stage DOUBLE-SYNC pipeline (proven; the
// single-sync variant lost 3x and is permanently retired), BK=32, reordered
// MMAs, ldmatrix.x4, __launch_bounds__(256,2) -> 128 regs, 2 CTAs/SM.
// MODE 5: FUSED q/k/v projections (bz selects); v-path writes TRANSPOSED
//         split V directly (g_vth/g_vtl) -> vtsplit kernel eliminated.
// MODE 1: QK^T; MODE 2: PV; MODE 3: Wo.
// ===========================================================================
__device__ __forceinline__ void mma16816(float* c, const uint32_t* a, const uint32_t* b)
{
    asm volatile(
        "mma.sync.aligned.m16n8k16.row.col.f32.bf16.bf16.f32 "
        "{%0,%1,%2,%3}, {%4,%5,%6,%7}, {%8,%9}, {%0,%1,%2,%3};\n"
        : "+f"(c[0]), "+f"(c[1]), "+f"(c[2]), "+f"(c[3])
        : "r"(a[0]), "r"(a[1]), "r"(a[2]), "r"(a[3]), "r"(b[0]), "r"(b[1]));
}

template <int MODE, int BN, int WM, int WN>
__global__ void __launch_bounds__(256, 2)
bmma2_k(const bf16* __restrict__ Ah_, const bf16* __restrict__ Al_,
        const bf16* __restrict__ Bh_, const bf16* __restrict__ Bl_,
        float* __restrict__ Cg, bf16* __restrict__ Oh, bf16* __restrict__ Ol,
        const float* __restrict__ bias, const float* __restrict__ resid,
        int K, int lda, int ldb, long sA, long sB, long sC)
{
    constexpr int BM = 128, LDS = 40;
    constexpr int WTM = BM / WM, WTN = BN / WN;
    constexpr int TI = WTM / 16, UI = WTN / 8;
    constexpr int A_ELE = BM * LDS;             // bf16 elems per A array
    constexpr int B_ELE = BN * LDS;
    constexpr int STAGE = 2 * A_ELE + 2 * B_ELE;  // bf16 elems per stage

    extern __shared__ bf16 smem[];              // 2 stages

    const int bx = blockIdx.x, by = blockIdx.y, bz = blockIdx.z;
    if (MODE == 1) { if (bx > by) return; }

    const bf16 *pAh, *pAl, *pBh, *pBl;
    if (MODE == 5) {
        if (bz == 0)      { pAh = g_aqh; pAl = g_aql; pBh = g_wqh; pBl = g_wql; }
        else if (bz == 1) { pAh = g_akh; pAl = g_akl; pBh = g_wqh; pBl = g_wql; }
        else              { pAh = g_avh; pAl = g_avl; pBh = g_wvh; pBl = g_wvl; }
    } else {
        pAh = Ah_ + (size_t)bz * sA;
        pAl = Al_ + (size_t)bz * sA;
        pBh = Bh_ + (size_t)bz * sB;
        pBl = Bl_ + (size_t)bz * sB;
    }

    const int m0 = by * BM, n0 = bx * BN;
    const int tid = threadIdx.x;
    const int warp = tid >> 5, lane = tid & 31;
    const int wm = warp / WN, wn = warp % WN;
    const int arow = tid >> 2;                  // 0..63
    const int acol = (tid & 3) * 8;             // 8-bf16 chunk

    const uint32_t smem_u = cvta_smem(smem);

    float acc[TI][UI][4];
#pragma unroll
    for (int t = 0; t < TI; t++)
#pragma unroll
        for (int u = 0; u < UI; u++)
#pragma unroll
            for (int r = 0; r < 4; r++) acc[t][u][r] = 0.f;

    const int kend = (MODE == 2) ? min(K, m0 + BM) : K;
    const int nch = kend >> 5;

    auto prefetch = [&](int c, int st) {
        const int k0 = c << 5;
        const uint32_t base = smem_u + (uint32_t)st * STAGE * 2;
#pragma unroll
        for (int it = 0; it < 2; it++) {
            int r = it * 64 + arow;
            uint32_t so = (uint32_t)(r * LDS + acol) * 2;
            size_t go = (size_t)(m0 + r) * lda + k0 + acol;
            cp16(base + so, pAh + go);
            cp16(base + A_ELE * 2 + so, pAl + go);
        }
#pragma unroll
        for (int it = 0; it < BN / 64; it++) {
            int r = it * 64 + arow;
            uint32_t so = (uint32_t)(r * LDS + acol) * 2;
            size_t go = (size_t)(n0 + r) * ldb + k0 + acol;
            cp16(base + 2 * A_ELE * 2 + so, pBh + go);
            cp16(base + (2 * A_ELE + B_ELE) * 2 + so, pBl + go);
        }
        cp_commit();
    };

    // ldmatrix lane geometry (constant per thread)
    const int a_row_f = lane & 15;              // row within 16-row fragment
    const int a_col_f = (lane >> 4) * 8;        // col half (0 / 8)
    const int b_row_f = (lane & 7) + ((lane >> 4) & 1) * 8;  // row within 16
    const int b_col_f = ((lane >> 3) & 1) * 8;  // col half (0 / 8)

    auto compute = [&](int st) {
        const uint32_t sbase  = smem_u + (uint32_t)st * STAGE * 2;
        const uint32_t aoff_h = sbase;
        const uint32_t aoff_l = sbase + A_ELE * 2;
        const uint32_t boff_h = sbase + 2 * A_ELE * 2;
        const uint32_t boff_l = sbase + (2 * A_ELE + B_ELE) * 2;
#pragma unroll
        for (int ks = 0; ks < 2; ks++) {
            const int c = ks * 16;
            uint32_t ah[TI][4], al[TI][4], bh[UI][2], bl[UI][2];
#pragma unroll
            for (int t = 0; t < TI; t++) {
                int r = wm * WTM + t * 16 + a_row_f;
                uint32_t off = (uint32_t)(r * LDS + c + a_col_f) * 2;
                ldsm4(ah[t], aoff_h + off);
                ldsm4(al[t], aoff_l + off);
            }
#pragma unroll
            for (int up = 0; up < UI / 2; up++) {
                int n = wn * WTN + up * 16 + b_row_f;
                uint32_t off = (uint32_t)(n * LDS + c + b_col_f) * 2;
                ldsm4(&bh[up * 2][0], boff_h + off);
                ldsm4(&bl[up * 2][0], boff_l + off);
            }
            // term-reordered: accumulator reuse spaced TI*UI mmas apart
#pragma unroll
            for (int t = 0; t < TI; t++)
#pragma unroll
                for (int u = 0; u < UI; u++) mma16816(acc[t][u], ah[t], bh[u]);
#pragma unroll
            for (int t = 0; t < TI; t++)
#pragma unroll
                for (int u = 0; u < UI; u++) mma16816(acc[t][u], al[t], bh[u]);
#pragma unroll
            for (int t = 0; t < TI; t++)
#pragma unroll
                for (int u = 0; u < UI; u++) mma16816(acc[t][u], ah[t], bl[u]);
        }
    };

    // proven 2-stage double-barrier pipeline (cp_wait<1> keeps overlap)
    prefetch(0, 0);
    for (int c = 0; c < nch; c++) {
        if (c + 1 < nch) { prefetch(c + 1, (c + 1) & 1); cp_wait<1>(); }
        else             { cp_wait<0>(); }
        __syncthreads();
        compute(c & 1);
        __syncthreads();
    }

    // ---- epilogue (pairs; n even) ----
#pragma unroll
    for (int t = 0; t < TI; t++) {
#pragma unroll
        for (int u = 0; u < UI; u++) {
            int m = m0 + wm * WTM + t * 16 + (lane >> 2);
            int n = n0 + wn * WTN + u * 8 + (lane & 3) * 2;
#pragma unroll
            for (int half = 0; half < 2; half++) {
                int mm = m + half * 8;
                float v0 = acc[t][u][half * 2 + 0];
                float v1 = acc[t][u][half * 2 + 1];
                if (MODE == 5) {
                    int b = mm >> 10, s = mm & 1023;
                    int h = n >> 6, dd = n & 63;
                    if (bz < 2) {                    // q/k: split bf16 store
                        size_t o = ((size_t)((b * 16 + h) * 1024 + s)) * 64 + dd;
                        bf16* OH = bz == 0 ? g_qh : g_kh;
                        bf16* OL = bz == 0 ? g_ql : g_kl;
                        bf16 h0, l0, h1, l1;
                        split1(v0 + bias[n], h0, l0);
                        split1(v1 + bias[n + 1], h1, l1);
                        *reinterpret_cast<uint32_t*>(&OH[o]) = pack2(h0, h1);
                        *reinterpret_cast<uint32_t*>(&OL[o]) = pack2(l0, l1);
                    } else {                         // v: TRANSPOSED split store
                        // V^T layout: [(b*16+h)*64+dd][s]  (bias in resid slot)
                        size_t o0 = ((size_t)((b * 16 + h) * 64 + dd)) * 1024 + s;
                        bf16 h0, l0, h1, l1;
                        split1(v0 + resid[n], h0, l0);
                        split1(v1 + resid[n + 1], h1, l1);
                        g_vth[o0] = h0;          g_vtl[o0] = l0;
                        g_vth[o0 + 1024] = h1;   g_vtl[o0 + 1024] = l1;
                    }
                } else if (MODE == 1) {              // scores
                    float* C = Cg + (size_t)bz * sC;
                    float2 o2 = make_float2(v0 * 0.125f, v1 * 0.125f);
                    *reinterpret_cast<float2*>(&C[(size_t)mm * 1024 + n]) = o2;
                } else if (MODE == 2) {              // split concat (PV)
                    int b = bz >> 4, hh = bz & 15;
                    size_t o = ((size_t)(b * 1024 + mm)) * 1024 + hh * 64 + n;
                    bf16 h0, l0, h1, l1;
                    split1(v0, h0, l0);
                    split1(v1, h1, l1);
                    *reinterpret_cast<uint32_t*>(&Oh[o]) = pack2(h0, h1);
                    *reinterpret_cast<uint32_t*>(&Ol[o]) = pack2(l0, l1);
                } else {                             // MODE 3: Wo
                    float2 rr = *reinterpret_cast<const float2*>(
                        &resid[(size_t)mm * 1024 + n]);
                    float2 o2 = make_float2(v0 + bias[n] + rr.x,
                                            v1 + bias[n + 1] + rr.y);
                    *reinterpret_cast<float2*>(&Cg[(size_t)mm * 1024 + n]) = o2;
                }
            }
        }
    }
}

// ---------------------------------------------------------------------------
// Row pass, TWO ROWS PER BLOCK (128 threads/row), one sync per reduction.
// Rows paired (i, 1023-i) for load balance. (Proven Round-13 shape.)
// ---------------------------------------------------------------------------
__global__ void __launch_bounds__(256)
rowpass2_k(float* __restrict__ S, const float* __restrict__ gammas,
           bf16* __restrict__ Ph, bf16* __restrict__ Pl)
{
    __shared__ float sm_m1[8], sm_s1[8], sm_t[16], sm_m2[8], sm_s2[8], sm_mx[8];

    const int tid  = threadIdx.x;
    const int g    = tid >> 7;                 // row group 0/1
    const int lt   = tid & 127;                // thread within group
    const int w    = lt >> 5;                  // warp within group 0..3
    const int lane = tid & 31;
    const int bx = blockIdx.x, bh = blockIdx.y;
    const int i = g ? (1023 - bx) : bx;
    const float gamma = -fabsf(gammas[bh & 15]);
    const size_t ro = ((size_t)bh << 20) + ((size_t)i << 10);
    float4* rowv = reinterpret_cast<float4*>(S + ro);

    const int ca = 4 * lt;                     // quad A cols [ca, ca+3]
    const int cb = 512 + 4 * lt;               // quad B cols
    const bool liveA = ca < i, liveB = cb < i;

    float sA[4] = {0.f, 0.f, 0.f, 0.f}, sB[4] = {0.f, 0.f, 0.f, 0.f};
    if (liveA) { float4 v = rowv[lt];       sA[0]=v.x; sA[1]=v.y; sA[2]=v.z; sA[3]=v.w; }
    if (liveB) { float4 v = rowv[128 + lt]; sB[0]=v.x; sB[1]=v.y; sB[2]=v.z; sB[3]=v.w; }

    float lgA[4], lgB[4];
#pragma unroll
    for (int l = 0; l < 4; l++) {
        lgA[l] = (ca + l < i) ? sA[l] : NEGF;
        lgB[l] = (cb + l < i) ? sB[l] : NEGF;
    }

    // ---- softmax-1 max (1 sync) ----
    float m = NEGF;
#pragma unroll
    for (int l = 0; l < 4; l++) m = fmaxf(m, fmaxf(lgA[l], lgB[l]));
#pragma unroll
    for (int o = 16; o; o >>= 1) m = fmaxf(m, __shfl_xor_sync(0xffffffffu, m, o));
    if (lane == 0) sm_m1[g * 4 + w] = m;
    __syncthreads();
    const float m1 = fmaxf(fmaxf(sm_m1[g*4+0], sm_m1[g*4+1]),
                           fmaxf(sm_m1[g*4+2], sm_m1[g*4+3]));

    // ---- exp + sum-1 (1 sync) ----
    float pA[4], pB[4];
    float s = 0.f;
#pragma unroll
    for (int l = 0; l < 4; l++) {
        pA[l] = __expf(lgA[l] - m1); s += pA[l];
        pB[l] = __expf(lgB[l] - m1); s += pB[l];
    }
#pragma unroll
    for (int o = 16; o; o >>= 1) s += __shfl_xor_sync(0xffffffffu, s, o);
    if (lane == 0) sm_s1[g * 4 + w] = s;
    __syncthreads();
    const float inv1 = 1.0f / (sm_s1[g*4+0] + sm_s1[g*4+1] + sm_s1[g*4+2] + sm_s1[g*4+3]);
#pragma unroll
    for (int l = 0; l < 4; l++) { pA[l] *= inv1; pB[l] *= inv1; }

    // ---- cumsum: warp scans + cross-warp prefix table (1 sync) ----
    const float localA = pA[0] + pA[1] + pA[2] + pA[3];
    const float localB = pB[0] + pB[1] + pB[2] + pB[3];
    float incA = localA, incB = localB;
#pragma unroll
    for (int o = 1; o < 32; o <<= 1) {
        float na = __shfl_up_sync(0xffffffffu, incA, o);
        float nb = __shfl_up_sync(0xffffffffu, incB, o);
        if (lane >= o) { incA += na; incB += nb; }
    }
    if (lane == 31) { sm_t[g * 8 + w] = incA; sm_t[g * 8 + 4 + w] = incB; }
    __syncthreads();
    float prevA = 0.f, prevB = 0.f;
    for (int w2 = 0; w2 < 4; w2++) {
        if (w2 < w) { prevA += sm_t[g * 8 + w2]; prevB += sm_t[g * 8 + 4 + w2]; }
    }
    const float totA = sm_t[g*8+0] + sm_t[g*8+1] + sm_t[g*8+2] + sm_t[g*8+3];
    const float totB = sm_t[g*8+4] + sm_t[g*8+5] + sm_t[g*8+6] + sm_t[g*8+7];
    const float preA = prevA + (incA - localA);
    const float preB = totA + prevB + (incB - localB);
    const float T = totA + totB;

    // ---- distance decay -> rescored logits ----
    float run = preA;
#pragma unroll
    for (int l = 0; l < 4; l++) {
        run += pA[l];
        float pe  = fabsf((float)(i - (ca + l)));
        float ds  = sqrtf(fmaxf(0.f, (T - run) * pe));
        float eff = fminf(fmaxf(__expf(ds * gamma), 1e-5f), 1e5f);
        lgA[l] = (ca + l < i) ? sA[l] * eff : NEGF;
    }
    run = preB;
#pragma unroll
    for (int l = 0; l < 4; l++) {
        run += pB[l];
        float pe  = fabsf((float)(i - (cb + l)));
        float ds  = sqrtf(fmaxf(0.f, (T - run) * pe));
        float eff = fminf(fmaxf(__expf(ds * gamma), 1e-5f), 1e5f);
        lgB[l] = (cb + l < i) ? sB[l] * eff : NEGF;
    }

    // ---- softmax-2 max (1 sync) ----
    m = NEGF;
#pragma unroll
    for (int l = 0; l < 4; l++) m = fmaxf(m, fmaxf(lgA[l], lgB[l]));
#pragma unroll
    for (int o = 16; o; o >>= 1) m = fmaxf(m, __shfl_xor_sync(0xffffffffu, m, o));
    if (lane == 0) sm_m2[g * 4 + w] = m;
    __syncthreads();
    const float m2 = fmaxf(fmaxf(sm_m2[g*4+0], sm_m2[g*4+1]),
                           fmaxf(sm_m2[g*4+2], sm_m2[g*4+3]));

    // ---- exp + sum-2 (1 sync) ----
    s = 0.f;
#pragma unroll
    for (int l = 0; l < 4; l++) {
        pA[l] = __expf(lgA[l] - m2); s += pA[l];
        pB[l] = __expf(lgB[l] - m2); s += pB[l];
    }
#pragma unroll
    for (int o = 16; o; o >>= 1) s += __shfl_xor_sync(0xffffffffu, s, o);
    if (lane == 0) sm_s2[g * 4 + w] = s;
    __syncthreads();
    const float inv2 = 1.0f / (sm_s2[g*4+0] + sm_s2[g*4+1] + sm_s2[g*4+2] + sm_s2[g*4+3]);

    // ---- zero-mask + row max (1 sync) ----
    float mx = 0.f;
#pragma unroll
    for (int l = 0; l < 4; l++) {
        pA[l] = (ca + l < i) ? pA[l] * inv2 : 0.f;
        pB[l] = (cb + l < i) ? pB[l] * inv2 : 0.f;
        mx = fmaxf(mx, fmaxf(pA[l], pB[l]));
    }
#pragma unroll
    for (int o = 16; o; o >>= 1) mx = fmaxf(mx, __shfl_xor_sync(0xffffffffu, mx, o));
    if (lane == 0) sm_mx[g * 4 + w] = mx;
    __syncthreads();
    const float mxr = fmaxf(fmaxf(sm_mx[g*4+0], sm_mx[g*4+1]),
                            fmaxf(sm_mx[g*4+2], sm_mx[g*4+3]));
    const float scale = fminf(1.0f / mxr, 5.0f);

    // ---- writes: full fp32 row (masked entries are exact 0); causal bf16 ----
    float4 ovA = make_float4(pA[0]*scale, pA[1]*scale, pA[2]*scale, pA[3]*scale);
    float4 ovB = make_float4(pB[0]*scale, pB[1]*scale, pB[2]*scale, pB[3]*scale);
    rowv[lt] = ovA;
    rowv[128 + lt] = ovB;
    if (liveA) {
        bf16 hh[4], ll[4];
#pragma unroll
        for (int l = 0; l < 4; l++) split1((&ovA.x)[l], hh[l], ll[l]);
        reinterpret_cast<uint2*>(Ph + ro)[lt] = *reinterpret_cast<uint2*>(hh);
        reinterpret_cast<uint2*>(Pl + ro)[lt] = *reinterpret_cast<uint2*>(ll);
    }
    if (liveB) {
        bf16 hh[4], ll[4];
#pragma unroll
        for (int l = 0; l < 4; l++) split1((&ovB.x)[l], hh[l], ll[l]);
        reinterpret_cast<uint2*>(Ph + ro)[128 + lt] = *reinterpret_cast<uint2*>(hh);
        reinterpret_cast<uint2*>(Pl + ro)[128 + lt] = *reinterpret_cast<uint2*>(ll);
    }
}

// ---------------------------------------------------------------------------
// block reduction helper (LN only)
// ---------------------------------------------------------------------------
template <bool IS_MAX>
__device__ __forceinline__ float blk_reduce(float v, float* red, int tid)
{
    const int lane = tid & 31, wid = tid >> 5;
#pragma unroll
    for (int o = 16; o; o >>= 1) {
        float t = __shfl_xor_sync(0xffffffffu, v, o);
        v = IS_MAX ? fmaxf(v, t) : (v + t);
    }
    __syncthreads();
    if (lane == 0) red[wid] = v;
    __syncthreads();
    if (tid == 0) {
        float r = red[0];
        for (int w = 1; w < 8; w++) r = IS_MAX ? fmaxf(r, red[w]) : (r + red[w]);
        red[8] = r;
    }
    __syncthreads();
    return red[8];
}

// ---------------------------------------------------------------------------
// LayerNorm over last dim (1024), one block per row.
// ---------------------------------------------------------------------------
__global__ void __launch_bounds__(256)
ln_k(const float* __restrict__ X, const float* __restrict__ w,
     const float* __restrict__ b, float* __restrict__ out)
{
    __shared__ float red[9];
    const int m = blockIdx.x, tid = threadIdx.x;
    const float* xr = X + (size_t)m * 1024u;

    float4 xv = reinterpret_cast<const float4*>(xr)[tid];
    float sx = xv.x + xv.y + xv.z + xv.w;
    float sq = xv.x * xv.x + xv.y * xv.y + xv.z * xv.z + xv.w * xv.w;

    float sum   = blk_reduce<false>(sx, red, tid);
    float sumsq = blk_reduce<false>(sq, red, tid);
    float mu   = sum * (1.0f / 1024.0f);
    float var  = sumsq * (1.0f / 1024.0f) - mu * mu;
    float rstd = rsqrtf(var + 1e-5f);

    float4 wv = reinterpret_cast<const float4*>(w)[tid];
    float4 bv = reinterpret_cast<const float4*>(b)[tid];
    float4 ov;
    ov.x = (xv.x - mu) * rstd * wv.x + bv.x;
    ov.y = (xv.y - mu) * rstd * wv.y + bv.y;
    ov.z = (xv.z - mu) * rstd * wv.z + bv.z;
    ov.w = (xv.w - mu) * rstd * wv.w + bv.w;
    reinterpret_cast<float4*>(out + (size_t)m * 1024u)[tid] = ov;
}

// ---------------------------------------------------------------------------
extern "C" void kernel_launch(void* const* d_in, const int* in_sizes, int n_in,
                              void* d_out, int out_size)
{
    const float* query  = (const float*)d_in[0];
    const float* key    = (const float*)d_in[1];
    const float* values = (const float*)d_in[2];
    const float* Wq     = (const float*)d_in[3];
    const float* bq     = (const float*)d_in[4];
    const float* Wv     = (const float*)d_in[5];
    const float* bv     = (const float*)d_in[6];
    const float* Wo     = (const float*)d_in[7];
    const float* bo     = (const float*)d_in[8];
    const float* gammas = (const float*)d_in[9];
    const float* ln_w   = (const float*)d_in[10];
    const float* ln_b   = (const float*)d_in[11];

    float* out    = (float*)d_out;                       // [4,1024,1024]
    float* scores = out + (size_t)4 * 1024 * 1024;       // [4,16,1024,1024]

    float* xp;
    cudaGetSymbolAddress((void**)&xp, g_x);

    bf16 *aqh,*aql,*akh,*akl,*avh,*avl;
    bf16 *qh,*ql,*kh,*kl,*vth,*vtl,*ch,*cl,*ph,*pl,*woh,*wol;
    cudaGetSymbolAddress((void**)&aqh, g_aqh); cudaGetSymbolAddress((void**)&aql, g_aql);
    cudaGetSymbolAddress((void**)&akh, g_akh); cudaGetSymbolAddress((void**)&akl, g_akl);
    cudaGetSymbolAddress((void**)&avh, g_avh); cudaGetSymbolAddress((void**)&avl, g_avl);
    cudaGetSymbolAddress((void**)&woh, g_woh); cudaGetSymbolAddress((void**)&wol, g_wol);
    cudaGetSymbolAddress((void**)&qh,  g_qh);  cudaGetSymbolAddress((void**)&ql,  g_ql);
    cudaGetSymbolAddress((void**)&kh,  g_kh);  cudaGetSymbolAddress((void**)&kl,  g_kl);
    cudaGetSymbolAddress((void**)&vth, g_vth); cudaGetSymbolAddress((void**)&vtl, g_vtl);
    cudaGetSymbolAddress((void**)&ch,  g_ch);  cudaGetSymbolAddress((void**)&cl,  g_cl);
    cudaGetSymbolAddress((void**)&ph,  g_ph);  cudaGetSymbolAddress((void**)&pl,  g_pl);

    const int NB4 = NBIG / 4 / 256;

    // dynamic smem sizes: 2 stages * (2*A + 2*B) * 40 * 2 bytes
    const int SM128 = 2 * (2 * 128 * 40 + 2 * 128 * 40) * 2;   // 81920
    const int SM64  = 2 * (2 * 128 * 40 + 2 * 64 * 40) * 2;    // 61440

    cudaFuncSetAttribute((const void*)bmma2_k<5, 128, 2, 4>,
        cudaFuncAttributeMaxDynamicSharedMemorySize, SM128);
    cudaFuncSetAttribute((const void*)bmma2_k<1, 128, 2, 4>,
        cudaFuncAttributeMaxDynamicSharedMemorySize, SM128);
    cudaFuncSetAttribute((const void*)bmma2_k<3, 128, 2, 4>,
        cudaFuncAttributeMaxDynamicSharedMemorySize, SM128);
    cudaFuncSetAttribute((const void*)bmma2_k<2, 64, 4, 2>,
        cudaFuncAttributeMaxDynamicSharedMemorySize, SM64);

    // 0) fused input split + fused weight transpose-splits
    split3_k<<<dim3(NB4, 3), 256>>>(query, key, values,
                                    aqh, aql, akh, akl, avh, avl);
    tsplit3_k<<<dim3(32, 32, 3), 256>>>(Wq, Wv, Wo);

    // 1) FUSED q/k/v projections; v-path writes transposed split V directly
    bmma2_k<5, 128, 2, 4><<<dim3(8, 32, 3), 256, SM128>>>(
        nullptr, nullptr, nullptr, nullptr, nullptr, nullptr, nullptr,
        bq, bv, 1024, 1024, 1024, 0, 0, 0);

    // 2) scores = Q K^T / 8 per head (causal block skip)
    bmma2_k<1, 128, 2, 4><<<dim3(8, 8, 64), 256, SM128>>>(
        qh, ql, kh, kl, scores, nullptr, nullptr, nullptr, nullptr,
        64, 64, 64, 1024L * 64, 1024L * 64, 1024L * 1024);

    // 3) row pass (2 rows/block, 6 syncs) -> fp32 scores + causal bf16 P
    rowpass2_k<<<dim3(512, 64), 256>>>(scores, gammas, ph, pl);

    // 4) concat = P @ V (causal K truncation, split output)
    bmma2_k<2, 64, 4, 2><<<dim3(1, 8, 64), 256, SM64>>>(
        ph, pl, vth, vtl, nullptr, ch, cl, nullptr, nullptr,
        1024, 1024, 1024, 1024L * 1024, 64L * 1024, 0);

    // 5) x = query + concat @ Wo + bo
    bmma2_k<3, 128, 2, 4><<<dim3(8, 32), 256, SM128>>>(
        ch, cl, woh, wol, xp, nullptr, nullptr,
        bo, query, 1024, 1024, 1024, 0, 0, 0);

    // 6) out = LayerNorm(x)
    ln_k<<<4096, 256>>>(xp, ln_w, ln_b, out);
}